// round 6
// baseline (speedup 1.0000x reference)
#include <cuda_runtime.h>
#include <cuda_fp16.h>
#include <cstdint>
#include <cstddef>

// ============================================================================
// SparseLinear via 2:4 sparse tensor cores (mma.sp), W is 95% sparse:
//   y^T[N,M] = WT(sparse A, compressed+meta) @ x^T(dense B), transpose-epilogue
//   with fused bias. Groups with >2 nonzeros spill residuals; exact fp32
//   fixup kernel applies them.
// R6 fix: correct m16n8k32 metadata thread layout — thread pair (T4q,T4q+1)
//   splits k (low/high 16 logical k), rows q / q+8 in low/high half-words.
//   Prep pre-interleaves metadata per 16-row block: g_metaI[nblk][k32][16].
// ============================================================================

#define D_DIM 4096
#define M_DIM 8192
#define BNR 128            // n' rows per CTA (sparse A side)
#define BMC 256            // m cols per CTA (dense B side = x rows)
#define BK 64
#define STAGES 4
#define KTILES (D_DIM / BK)            // 64
#define THREADS 256
#define A_BYTES 16384      // 128 rows x 128B (64B data + swizzle pad)
#define B_BYTES 32768      // 256 rows x 128B
#define META_BYTES 1024    // 8 blk x 2 steps x 16 u32
#define STAGE_BYTES (A_BYTES + B_BYTES + META_BYTES)   // 50176
#define SMEM_SIZE (STAGES * STAGE_BYTES)               // 200704
#define RESMAX 262144

__device__ __align__(256) __half g_XH[(size_t)M_DIM * D_DIM];        // x fp16 [M,K]
__device__ __align__(256) __half g_WTc[(size_t)D_DIM * (D_DIM / 2)]; // compressed WT [N, K/2]
// interleaved metadata: [n/16][k/32][16 u32]  (per-thread-ready format)
__device__ __align__(256) uint32_t g_metaI[(size_t)(D_DIM / 16) * (D_DIM / 32) * 16];
__device__ uint4 g_res[RESMAX];
__device__ unsigned int g_rescnt;

// ---------------------------------------------------------------------------
__device__ __forceinline__ uint32_t smem_u32(const void* p) {
    uint32_t a;
    asm("{ .reg .u64 t; cvta.to.shared.u64 t, %1; cvt.u32.u64 %0, t; }"
        : "=r"(a) : "l"(p));
    return a;
}
__device__ __forceinline__ void cp_async16(uint32_t dst, const void* src) {
    asm volatile("cp.async.cg.shared.global [%0], [%1], 16;"
                 :: "r"(dst), "l"(src));
}
__device__ __forceinline__ void cp_commit() {
    asm volatile("cp.async.commit_group;" ::: "memory");
}
__device__ __forceinline__ void ldsm_x4(uint32_t* r, uint32_t addr) {
    asm volatile("ldmatrix.sync.aligned.m8n8.x4.shared.b16 {%0,%1,%2,%3}, [%4];"
                 : "=r"(r[0]), "=r"(r[1]), "=r"(r[2]), "=r"(r[3])
                 : "r"(addr));
}
// sparse mma: D = A(16x32 2:4) * B(32x8) + C, fp16 in, fp32 acc, selector 0
__device__ __forceinline__ void spmma(float* c, const uint32_t* a,
                                      uint32_t b0, uint32_t b1,
                                      uint32_t b2, uint32_t b3, uint32_t e) {
    asm volatile(
        "mma.sp::ordered_metadata.sync.aligned.m16n8k32.row.col.f32.f16.f16.f32 "
        "{%0,%1,%2,%3}, {%4,%5,%6,%7}, {%8,%9,%10,%11}, {%0,%1,%2,%3}, %12, 0x0;"
        : "+f"(c[0]), "+f"(c[1]), "+f"(c[2]), "+f"(c[3])
        : "r"(a[0]), "r"(a[1]), "r"(a[2]), "r"(a[3]),
          "r"(b0), "r"(b1), "r"(b2), "r"(b3), "r"(e));
}

// ---------------------------------------------------------------------------
// K1: reset residual counter (graph replays!)
// ---------------------------------------------------------------------------
__global__ void zero_kernel() { g_rescnt = 0; }

// ---------------------------------------------------------------------------
// K2 prep: blocks [0,XBLK): x->fp16. Rest: 32x32 W tiles -> compress + meta.
// ---------------------------------------------------------------------------
#define XBLK ((int)((size_t)M_DIM * D_DIM / 4 / 256))   // 32768

__global__ void prep_kernel(const float4* __restrict__ x,
                            const float* __restrict__ W) {
    if (blockIdx.x < XBLK) {
        size_t i = (size_t)blockIdx.x * 256 + threadIdx.x;
        float4 v = x[i];
        __half2 h0 = __floats2half2_rn(v.x, v.y);
        __half2 h1 = __floats2half2_rn(v.z, v.w);
        uint2 o;
        o.x = *reinterpret_cast<uint32_t*>(&h0);
        o.y = *reinterpret_cast<uint32_t*>(&h1);
        reinterpret_cast<uint2*>(g_XH)[i] = o;
        return;
    }
    __shared__ float t[32][33];         // t[k_local][n_local]
    __shared__ uint32_t metas[32];      // per n-row 32-bit meta (k32)
    int b = blockIdx.x - XBLK;                     // 128x128 tile grid
    int bx = (b & 127) * 32, by = (b >> 7) * 32;   // bx: n, by: k
    int tx = threadIdx.x & 31, ty = threadIdx.x >> 5;
#pragma unroll
    for (int i = 0; i < 32; i += 8)
        t[ty + i][tx] = W[(size_t)(by + ty + i) * D_DIM + bx + tx];
    if (threadIdx.x < 32) metas[threadIdx.x] = 0;
    __syncthreads();

    const int nl = threadIdx.x >> 3;    // 0..31 local n row
    const int grp = threadIdx.x & 7;    // 0..7 group of 4 k
    float v[4];
#pragma unroll
    for (int j = 0; j < 4; j++) v[j] = t[4 * grp + j][nl];

    int p0 = -1, p1 = -1;
#pragma unroll
    for (int j = 0; j < 4; j++) {
        if (v[j] != 0.0f) {
            if (p0 < 0) p0 = j;
            else if (p1 < 0) p1 = j;
            else {  // 3rd/4th nonzero -> residual
                unsigned idx = atomicAdd(&g_rescnt, 1u);
                if (idx < RESMAX)
                    g_res[idx] = make_uint4((unsigned)(bx + nl),
                                            (unsigned)(by + 4 * grp + j),
                                            __float_as_uint(v[j]), 0u);
            }
        }
    }
    if (p0 < 0) { p0 = 0; p1 = 1; }
    else if (p1 < 0) { if (p0 == 3) { p0 = 2; p1 = 3; } else p1 = 3; }

    __half2 hv = __floats2half2_rn(v[p0], v[p1]);
    reinterpret_cast<uint32_t*>(g_WTc)[(size_t)(bx + nl) * 1024 + by / 4 + grp] =
        *reinterpret_cast<uint32_t*>(&hv);
    atomicOr(&metas[nl], (uint32_t)(p0 | (p1 << 2)) << (4 * grp));
    __syncthreads();

    // Interleave to per-thread format. For 16-row block blk, entry t:
    //   q = t>>1 (quad row), kh = t&1 (k half):
    //   E = rowq.kh16 | rowq8.kh16 << 16
    if (threadIdx.x < 32) {
        int blk = threadIdx.x >> 4;     // 0/1 within the 32-row tile
        int t16 = threadIdx.x & 15;
        int q = t16 >> 1, kh = t16 & 1;
        uint32_t lo = (metas[blk * 16 + q]     >> (16 * kh)) & 0xFFFFu;
        uint32_t hi = (metas[blk * 16 + q + 8] >> (16 * kh)) & 0xFFFFu;
        g_metaI[(size_t)((bx >> 4) + blk) * (128 * 16) + (by >> 5) * 16 + t16] =
            lo | (hi << 16);
    }
}

// ---------------------------------------------------------------------------
// K3: sparse GEMM. grid (N/128, M/256) = (32,32), 256 thr = 8 warps (2n' x 4m)
// y^T tile [128 n'] x [256 m]; warp tile 64x64; ktile k64 = 2 sp steps (k32).
// ---------------------------------------------------------------------------
__global__ __launch_bounds__(THREADS, 1)
void gemm_sp_kernel(const float* __restrict__ bias, float* __restrict__ out) {
    extern __shared__ char smem[];
    const uint32_t sbase = smem_u32(smem);
    const int tid = threadIdx.x;
    const int wid = tid >> 5;
    const int l = tid & 31;
    const int bn = blockIdx.x * BNR;   // n' block (A rows)
    const int bm = blockIdx.y * BMC;   // m block (B rows = x rows)
    const int wn = (wid >> 2) * 64;    // warp n' offset
    const int wm = (wid & 3) * 64;     // warp m offset

    // ---- tile loaders ----
    auto load_tile = [&](int kt, int slot) {
        const uint32_t sb = sbase + (uint32_t)slot * STAGE_BYTES;
        // A: 512 granules (128 rows x 4x16B), 2 per thread
#pragma unroll
        for (int j = 0; j < 2; j++) {
            int gi = tid + j * 256;
            int r = gi >> 2, g = gi & 3;
            const char* src = (const char*)g_WTc +
                (size_t)(bn + r) * 4096 + kt * 64 + g * 16;
            cp_async16(sb + (uint32_t)(r * 128) +
                       ((uint32_t)(g ^ (r & 7)) << 4), src);
        }
        // meta: 8 blocks x (2 steps x 16 u32 = 128B contiguous), 64 granules
        if (tid < 64) {
            int blk = tid >> 3, g = tid & 7;
            const char* src = (const char*)g_metaI +
                (size_t)(bn / 16 + blk) * (128 * 16 * 4) + kt * 128 + g * 16;
            cp_async16(sb + A_BYTES + B_BYTES + (uint32_t)(tid * 16), src);
        }
        // B: 2048 granules (256 rows x 8x16B), 8 per thread
#pragma unroll
        for (int j = 0; j < 8; j++) {
            int gi = tid + j * 256;
            int r = gi >> 3, g = gi & 7;
            const char* src = (const char*)g_XH +
                (size_t)(bm + r) * 8192 + kt * 128 + g * 16;
            cp_async16(sb + A_BYTES + (uint32_t)(r * 128) +
                       ((uint32_t)(g ^ (r & 7)) << 4), src);
        }
    };

    // ---- fragment loaders ----
    const int arow_l = (l & 15);
    const int agr = (l >> 4);
    const int brow_off = (l & 7) + ((l >> 4) << 3);
    const int bkg0 = (l >> 3) & 1;
    // per-thread metadata slot within a 16-row block: q*2 + khalf
    const uint32_t eoff = (uint32_t)((((l >> 2) << 1) | (l & 1)) << 2);

    auto ldA = [&](uint32_t stg, int s, uint32_t (&A)[4][4], uint32_t (&E)[4]) {
#pragma unroll
        for (int mt = 0; mt < 4; mt++) {
            int row = wn + mt * 16 + arow_l;
            ldsm_x4(A[mt], stg + (uint32_t)(row * 128) +
                    ((uint32_t)((2 * s + agr) ^ (row & 7)) << 4));
            asm volatile("ld.shared.u32 %0, [%1];" : "=r"(E[mt])
                : "r"(stg + A_BYTES + B_BYTES +
                      (uint32_t)(((wn >> 4) + mt) * 128 + s * 64) + eoff));
        }
    };
    auto ldB = [&](uint32_t stg, int s, int pp, uint32_t (&Bf)[2][4]) {
#pragma unroll
        for (int kg = 0; kg < 2; kg++) {
            int row = wm + pp * 16 + brow_off;
            ldsm_x4(Bf[kg], stg + A_BYTES + (uint32_t)(row * 128) +
                    ((uint32_t)((2 * (2 * s + kg) + bkg0) ^ (row & 7)) << 4));
        }
    };

    float acc[4][8][4] = {};
    auto mma_pp = [&](uint32_t (&A)[4][4], uint32_t (&E)[4],
                      uint32_t (&Bf)[2][4], int pp) {
#pragma unroll
        for (int mt = 0; mt < 4; mt++) {
            spmma(acc[mt][2 * pp],     A[mt], Bf[0][0], Bf[0][1],
                  Bf[1][0], Bf[1][1], E[mt]);
            spmma(acc[mt][2 * pp + 1], A[mt], Bf[0][2], Bf[0][3],
                  Bf[1][2], Bf[1][3], E[mt]);
        }
    };

    // ---- prologue ----
#pragma unroll
    for (int s = 0; s < STAGES - 1; s++) { load_tile(s, s); cp_commit(); }
    asm volatile("cp.async.wait_group %0;" :: "n"(STAGES - 2) : "memory");
    __syncthreads();

    uint32_t Ab[2][4][4], Em[2][4], Bf[2][2][4];
    ldA(sbase, 0, Ab[0], Em[0]);
    ldB(sbase, 0, 0, Bf[0]);

    for (int kt = 0; kt < KTILES; kt++) {
        const uint32_t stg = sbase + (uint32_t)(kt & 3) * STAGE_BYTES;
        const int pf = kt + STAGES - 1;
        if (pf < KTILES) load_tile(pf, pf & 3);
        cp_commit();

        // step s=0
        ldB(stg, 0, 1, Bf[1]);
        ldA(stg, 1, Ab[1], Em[1]);
        mma_pp(Ab[0], Em[0], Bf[0], 0);
        ldB(stg, 0, 2, Bf[0]);  mma_pp(Ab[0], Em[0], Bf[1], 1);
        ldB(stg, 0, 3, Bf[1]);  mma_pp(Ab[0], Em[0], Bf[0], 2);
        ldB(stg, 1, 0, Bf[0]);  mma_pp(Ab[0], Em[0], Bf[1], 3);
        // step s=1
        ldB(stg, 1, 1, Bf[1]);  mma_pp(Ab[1], Em[1], Bf[0], 0);
        ldB(stg, 1, 2, Bf[0]);  mma_pp(Ab[1], Em[1], Bf[1], 1);
        ldB(stg, 1, 3, Bf[1]);  mma_pp(Ab[1], Em[1], Bf[0], 2);
        mma_pp(Ab[1], Em[1], Bf[1], 3);

        asm volatile("cp.async.wait_group %0;" :: "n"(STAGES - 2) : "memory");
        __syncthreads();
        if (kt + 1 < KTILES) {
            const uint32_t nstg = sbase + (uint32_t)((kt + 1) & 3) * STAGE_BYTES;
            ldA(nstg, 0, Ab[0], Em[0]);
            ldB(nstg, 0, 0, Bf[0]);
        }
    }

    // ---- epilogue: transpose y^T tile through SMEM, add bias ----
    float* ys = reinterpret_cast<float*>(smem);   // [128][257]
    const int q = l >> 2, tig = l & 3;
#pragma unroll
    for (int mt = 0; mt < 4; mt++) {
        int r0 = wn + mt * 16 + q;
#pragma unroll
        for (int p = 0; p < 8; p++) {
            int c0 = wm + p * 8 + tig * 2;
            ys[r0 * 257 + c0]           = acc[mt][p][0];
            ys[r0 * 257 + c0 + 1]       = acc[mt][p][1];
            ys[(r0 + 8) * 257 + c0]     = acc[mt][p][2];
            ys[(r0 + 8) * 257 + c0 + 1] = acc[mt][p][3];
        }
    }
    __syncthreads();

    float bb[4];
#pragma unroll
    for (int cc = 0; cc < 4; cc++) bb[cc] = bias[bn + cc * 32 + l];
#pragma unroll 4
    for (int rr = 0; rr < 32; rr++) {
        int ml = wid * 32 + rr;
        float* orow = out + (size_t)(bm + ml) * D_DIM + bn;
#pragma unroll
        for (int cc = 0; cc < 4; cc++)
            orow[cc * 32 + l] = ys[(cc * 32 + l) * 257 + ml] + bb[cc];
    }
}

// ---------------------------------------------------------------------------
// K4: exact fp32 fixup for spilled residuals: y[:,n] += x[:,k] * w
// ---------------------------------------------------------------------------
__global__ void fixup_kernel(const float* __restrict__ x,
                             float* __restrict__ y) {
    unsigned L = g_rescnt;
    if (L > RESMAX) L = RESMAX;
    for (unsigned r = blockIdx.x; r < L; r += gridDim.x) {
        uint4 e = g_res[r];
        const unsigned n = e.x, k = e.y;
        const float w = __uint_as_float(e.z);
        for (int m = threadIdx.x; m < M_DIM; m += 256)
            atomicAdd(&y[(size_t)m * D_DIM + n], x[(size_t)m * D_DIM + k] * w);
    }
}

// ---------------------------------------------------------------------------
extern "C" void kernel_launch(void* const* d_in, const int* in_sizes, int n_in,
                              void* d_out, int out_size) {
    const float* x    = (const float*)d_in[0];
    const float* W    = (const float*)d_in[1];
    const float* bias = (const float*)d_in[2];
    float* out = (float*)d_out;

    cudaFuncSetAttribute(gemm_sp_kernel,
                         cudaFuncAttributeMaxDynamicSharedMemorySize, SMEM_SIZE);

    zero_kernel<<<1, 1>>>();
    prep_kernel<<<XBLK + 128 * 128, 256>>>((const float4*)x, W);
    gemm_sp_kernel<<<dim3(D_DIM / BNR, M_DIM / BMC), THREADS, SMEM_SIZE>>>(
        bias, out);
    fixup_kernel<<<2048, 256>>>(x, out);
}

// round 8
// speedup vs baseline: 1.2625x; 1.2625x over previous
#include <cuda_runtime.h>
#include <cuda_fp16.h>
#include <cstdint>
#include <cstddef>

// ============================================================================
// SparseLinear: y[8192,4096] = x[8192,4096] @ W[4096,4096] + bias[4096]
// Dense fp16 mma.sync GEMM (tcgen05 blocked by compute_103 PTX target;
// mma.sp measured at dense rate on sm_103a legacy path -> sparse dead end).
// R7: persistent CTAs (grid=148) with a cross-tile continuous cp.async
//     stream (pipeline never drains), prefetch spread 3 granules per ks step
//     (no LSU burst), frag preload hidden under the epilogue.
// ============================================================================

#define D_DIM 4096
#define M_DIM 8192
#define BM 128
#define BN 256
#define BK 64
#define KTILES 64
#define THREADS 256
#define SMS 148
#define NTILES 1024                     // (M/BM)*(N/BN) = 64*16
#define A_TILE_BYTES (BM * BK * 2)      // 16384
#define B_TILE_BYTES (BN * BK * 2)      // 32768
#define STAGE_BYTES (A_TILE_BYTES + B_TILE_BYTES)   // 49152
#define SMEM_SIZE (4 * STAGE_BYTES)                 // 196608

__device__ __align__(256) __half g_XH[(size_t)M_DIM * D_DIM];
__device__ __align__(256) __half g_WTH[(size_t)D_DIM * D_DIM];

// ---------------------------------------------------------------------------
__device__ __forceinline__ uint32_t smem_u32(const void* p) {
    uint32_t a;
    asm("{ .reg .u64 t; cvta.to.shared.u64 t, %1; cvt.u32.u64 %0, t; }"
        : "=r"(a) : "l"(p));
    return a;
}
__device__ __forceinline__ void cp_async16(uint32_t dst, const void* src) {
    asm volatile("cp.async.cg.shared.global [%0], [%1], 16;"
                 :: "r"(dst), "l"(src));
}
__device__ __forceinline__ void cp_commit() {
    asm volatile("cp.async.commit_group;" ::: "memory");
}
__device__ __forceinline__ void ldsm_x4(uint32_t* r, uint32_t addr) {
    asm volatile("ldmatrix.sync.aligned.m8n8.x4.shared.b16 {%0,%1,%2,%3}, [%4];"
                 : "=r"(r[0]), "=r"(r[1]), "=r"(r[2]), "=r"(r[3])
                 : "r"(addr));
}
__device__ __forceinline__ void mma16816(float* c, const uint32_t* a,
                                         uint32_t b0, uint32_t b1) {
    asm volatile(
        "mma.sync.aligned.m16n8k16.row.col.f32.f16.f16.f32 "
        "{%0,%1,%2,%3}, {%4,%5,%6,%7}, {%8,%9}, {%0,%1,%2,%3};"
        : "+f"(c[0]), "+f"(c[1]), "+f"(c[2]), "+f"(c[3])
        : "r"(a[0]), "r"(a[1]), "r"(a[2]), "r"(a[3]), "r"(b0), "r"(b1));
}

// ---------------------------------------------------------------------------
// Merged prep: blocks [0, XBLK) convert x -> fp16; rest transpose+convert W.
// ---------------------------------------------------------------------------
#define XBLK ((int)((size_t)M_DIM * D_DIM / 4 / 256))   // 32768

__global__ void prep_kernel(const float4* __restrict__ x,
                            const float* __restrict__ W) {
    if (blockIdx.x < XBLK) {
        size_t i = (size_t)blockIdx.x * 256 + threadIdx.x;
        float4 v = x[i];
        __half2 h0 = __floats2half2_rn(v.x, v.y);
        __half2 h1 = __floats2half2_rn(v.z, v.w);
        uint2 o;
        o.x = *reinterpret_cast<uint32_t*>(&h0);
        o.y = *reinterpret_cast<uint32_t*>(&h1);
        reinterpret_cast<uint2*>(g_XH)[i] = o;
    } else {
        __shared__ float t[32][33];
        int b = blockIdx.x - XBLK;                     // 128 x 128 tile grid
        int bx = (b & 127) * 32, by = (b >> 7) * 32;   // bx: n, by: k
        int tx = threadIdx.x & 31, ty = threadIdx.x >> 5;
#pragma unroll
        for (int i = 0; i < 32; i += 8)
            t[ty + i][tx] = W[(size_t)(by + ty + i) * D_DIM + bx + tx];
        __syncthreads();
#pragma unroll
        for (int i = 0; i < 32; i += 8)
            g_WTH[(size_t)(bx + ty + i) * D_DIM + by + tx] =
                __float2half_rn(t[tx][ty + i]);
    }
}

// ---------------------------------------------------------------------------
// Persistent GEMM. grid = 148 CTAs; CTA b owns tiles b, b+148, ... < 1024.
// Global ktile stream g: tile = bid + (g>>6)*148, kt = g&63. Loads run 3
// ahead of compute, crossing tile boundaries (pipeline never drains).
// ---------------------------------------------------------------------------
__global__ __launch_bounds__(THREADS, 1)
void gemm_f16_kernel(const float* __restrict__ bias, float* __restrict__ out) {
    extern __shared__ char smem[];
    const uint32_t sbase = smem_u32(smem);
    const int tid = threadIdx.x;
    const int wid = tid >> 5;
    const int l = tid & 31;
    const int bid = blockIdx.x;
    const int wm = (wid >> 2) * 64;   // 2 warps in m
    const int wn = (wid & 3) * 64;    // 4 warps in n

    const int my_ntiles = (NTILES - bid + SMS - 1) / SMS;
    const int gmax = my_ntiles * KTILES;

    // fixed per-thread cp.async pattern
    const int lrow = tid >> 3;         // 0..31 (rows step 32 per granule)
    const int lcol = (tid & 7) * 8;    // halves within 64-k row
    const uint32_t sdst0 = (uint32_t)(lrow * 128) +
                           ((uint32_t)((tid & 7) ^ (lrow & 7)) << 4);

    // loader for stream index lg: returns base pointers (halves)
    auto loader_bases = [&](int lg, const __half*& ap, const __half*& bp) {
        int tile = bid + (lg >> 6) * SMS;
        int kt = lg & 63;
        int bml = (tile >> 4) * BM;
        int bnl = (tile & 15) * BN;
        ap = g_XH + (size_t)(bml + lrow) * D_DIM + kt * BK + lcol;
        bp = g_WTH + (size_t)(bnl + lrow) * D_DIM + kt * BK + lcol;
    };
    // granule s of current load tile: s<4 -> A, else B
    auto issue_granule = [&](int s, const __half* ap, const __half* bp,
                             uint32_t sb) {
        if (s < 4)
            cp_async16(sb + sdst0 + (uint32_t)(s * 4096),
                       ap + (size_t)s * 32 * D_DIM);
        else {
            int j = s - 4;
            cp_async16(sb + A_TILE_BYTES + sdst0 + (uint32_t)(j * 4096),
                       bp + (size_t)j * 32 * D_DIM);
        }
    };

    // --- fragment addressing (R4-proven) ---
    const int arow_l = (l & 15);
    const int agr = (l >> 4);
    const int brow_off = (l & 7) + ((l >> 4) << 3);
    const int bkg0 = (l >> 3) & 1;
    const uint32_t a_base = (uint32_t)((wm + arow_l) * 128);
    const uint32_t b_base = (uint32_t)((wn + brow_off) * 128) + A_TILE_BYTES;
    const uint32_t kxor = (uint32_t)(l & 7);

    auto load_frags = [&](uint32_t stg, int ks,
                          uint32_t (&A)[4][4], uint32_t (&B)[4][4]) {
#pragma unroll
        for (int mt = 0; mt < 4; mt++)
            ldsm_x4(A[mt], stg + a_base + mt * 2048 +
                           ((((uint32_t)(2 * ks) + agr) ^ kxor) << 4));
#pragma unroll
        for (int p = 0; p < 4; p++)
            ldsm_x4(B[p], stg + b_base + p * 2048 +
                          ((((uint32_t)(2 * ks) + bkg0) ^ kxor) << 4));
    };

    float acc[4][8][4] = {};
    uint32_t Abuf[2][4][4], Bbuf[2][4][4];

    auto mma_all = [&](uint32_t (&A)[4][4], uint32_t (&B)[4][4]) {
#pragma unroll
        for (int mt = 0; mt < 4; mt++)
#pragma unroll
            for (int p = 0; p < 4; p++) {
                mma16816(acc[mt][2 * p],     A[mt], B[p][0], B[p][1]);
                mma16816(acc[mt][2 * p + 1], A[mt], B[p][2], B[p][3]);
            }
    };

    // --- prologue: stream loads g=0,1,2 ---
#pragma unroll
    for (int p = 0; p < 3; p++) {
        const __half *ap, *bp;
        loader_bases(p, ap, bp);
        const uint32_t sb = sbase + (uint32_t)p * STAGE_BYTES;
#pragma unroll
        for (int s = 0; s < 12; s++) issue_granule(s, ap, bp, sb);
        cp_commit();
    }
    asm volatile("cp.async.wait_group 2;" ::: "memory");
    __syncthreads();
    load_frags(sbase, 0, Abuf[0], Bbuf[0]);

    // --- main stream loop ---
    for (int g = 0; g < gmax; g++) {
        const uint32_t stg = sbase + (uint32_t)(g & 3) * STAGE_BYTES;
        const int lg = g + 3;
        const bool lvalid = lg < gmax;
        const __half *ap = nullptr, *bp = nullptr;
        uint32_t lsb = sbase + (uint32_t)(lg & 3) * STAGE_BYTES;
        if (lvalid) loader_bases(lg, ap, bp);

#pragma unroll
        for (int ks = 0; ks < 4; ks++) {
            if (lvalid) {   // spread prefetch: 3 granules per ks step
                issue_granule(3 * ks + 0, ap, bp, lsb);
                issue_granule(3 * ks + 1, ap, bp, lsb);
                issue_granule(3 * ks + 2, ap, bp, lsb);
            }
            if (ks < 3)
                load_frags(stg, ks + 1, Abuf[(ks + 1) & 1], Bbuf[(ks + 1) & 1]);
            mma_all(Abuf[ks & 1], Bbuf[ks & 1]);
        }
        cp_commit();
        asm volatile("cp.async.wait_group 2;" ::: "memory");
        __syncthreads();

        if (g + 1 < gmax)
            load_frags(sbase + (uint32_t)((g + 1) & 3) * STAGE_BYTES, 0,
                       Abuf[0], Bbuf[0]);

        if ((g & 63) == 63) {
            // --- epilogue for finished tile (overlaps in-flight loads) ---
            const int tile = bid + (g >> 6) * SMS;
            const int bm = (tile >> 4) * BM;
            const int bn = (tile & 15) * BN;
            const int grp = l >> 2, tig = l & 3;
#pragma unroll
            for (int mt = 0; mt < 4; mt++) {
                const size_t row0 = (size_t)(bm + wm + mt * 16 + grp);
#pragma unroll
                for (int nt = 0; nt < 8; nt++) {
                    const int col = bn + wn + nt * 8 + tig * 2;
                    const float2 bv =
                        *reinterpret_cast<const float2*>(bias + col);
                    float2 v0, v1;
                    v0.x = acc[mt][nt][0] + bv.x;
                    v0.y = acc[mt][nt][1] + bv.y;
                    v1.x = acc[mt][nt][2] + bv.x;
                    v1.y = acc[mt][nt][3] + bv.y;
                    *reinterpret_cast<float2*>(out + row0 * D_DIM + col) = v0;
                    *reinterpret_cast<float2*>(
                        out + (row0 + 8) * D_DIM + col) = v1;
                    acc[mt][nt][0] = 0.0f; acc[mt][nt][1] = 0.0f;
                    acc[mt][nt][2] = 0.0f; acc[mt][nt][3] = 0.0f;
                }
            }
        }
    }
}

// ---------------------------------------------------------------------------
// Launch
// ---------------------------------------------------------------------------
extern "C" void kernel_launch(void* const* d_in, const int* in_sizes, int n_in,
                              void* d_out, int out_size) {
    const float* x    = (const float*)d_in[0];
    const float* W    = (const float*)d_in[1];
    const float* bias = (const float*)d_in[2];
    float* out = (float*)d_out;

    cudaFuncSetAttribute(gemm_f16_kernel,
                         cudaFuncAttributeMaxDynamicSharedMemorySize, SMEM_SIZE);

    prep_kernel<<<XBLK + 128 * 128, 256>>>((const float4*)x, W);
    gemm_f16_kernel<<<SMS, THREADS, SMEM_SIZE>>>(bias, out);
}

// round 12
// speedup vs baseline: 1.5471x; 1.2254x over previous
#include <cuda_runtime.h>
#include <cuda_fp16.h>
#include <cstdint>
#include <cstddef>

// ============================================================================
// SparseLinear: y[8192,4096] = x[8192,4096] @ W[4096,4096] + bias[4096]
// Dense fp16 mma.sync GEMM (tcgen05 blocked by compute_103 PTX target;
// mma.sp measured at dense rate -> sparse path dead; persistent CTAs
// regressed via mainloop ALU -> reverted).
// R9 = R4 + spread prefetch: the 12 cp.async granules per ktile are issued
//      4-at-a-time at ks=0/1/2 with precomputed bases + constant offsets,
//      removing the tile-start LSU burst that collided with fragment ldsm.
// ============================================================================

#define D_DIM 4096
#define M_DIM 8192
#define BM 128
#define BN 256
#define BK 64
#define STAGES 4
#define KTILES (D_DIM / BK)            // 64
#define THREADS 256
#define A_TILE_BYTES (BM * BK * 2)     // 16384
#define B_TILE_BYTES (BN * BK * 2)     // 32768
#define STAGE_BYTES (A_TILE_BYTES + B_TILE_BYTES)   // 49152
#define SMEM_SIZE (STAGES * STAGE_BYTES)            // 196608

__device__ __align__(256) __half g_XH[(size_t)M_DIM * D_DIM];
__device__ __align__(256) __half g_WTH[(size_t)D_DIM * D_DIM];

// ---------------------------------------------------------------------------
// helpers
// ---------------------------------------------------------------------------
__device__ __forceinline__ uint32_t smem_u32(const void* p) {
    uint32_t a;
    asm("{ .reg .u64 t; cvta.to.shared.u64 t, %1; cvt.u32.u64 %0, t; }"
        : "=r"(a) : "l"(p));
    return a;
}

__device__ __forceinline__ void cp_async16(uint32_t dst, const void* src) {
    asm volatile("cp.async.cg.shared.global [%0], [%1], 16;"
                 :: "r"(dst), "l"(src));
}
__device__ __forceinline__ void cp_commit() {
    asm volatile("cp.async.commit_group;" ::: "memory");
}

__device__ __forceinline__ void ldsm_x4(uint32_t* r, uint32_t addr) {
    asm volatile("ldmatrix.sync.aligned.m8n8.x4.shared.b16 {%0,%1,%2,%3}, [%4];"
                 : "=r"(r[0]), "=r"(r[1]), "=r"(r[2]), "=r"(r[3])
                 : "r"(addr));
}

__device__ __forceinline__ void mma16816(float* c, const uint32_t* a,
                                         uint32_t b0, uint32_t b1) {
    asm volatile(
        "mma.sync.aligned.m16n8k16.row.col.f32.f16.f16.f32 "
        "{%0,%1,%2,%3}, {%4,%5,%6,%7}, {%8,%9}, {%0,%1,%2,%3};"
        : "+f"(c[0]), "+f"(c[1]), "+f"(c[2]), "+f"(c[3])
        : "r"(a[0]), "r"(a[1]), "r"(a[2]), "r"(a[3]), "r"(b0), "r"(b1));
}

// ---------------------------------------------------------------------------
// Merged prep: blocks [0, XBLK) convert x -> fp16; rest transpose+convert W.
// ---------------------------------------------------------------------------
#define XBLK ((int)((size_t)M_DIM * D_DIM / 4 / 256))   // 32768

__global__ void prep_kernel(const float4* __restrict__ x,
                            const float* __restrict__ W) {
    if (blockIdx.x < XBLK) {
        size_t i = (size_t)blockIdx.x * 256 + threadIdx.x;
        float4 v = x[i];
        __half2 h0 = __floats2half2_rn(v.x, v.y);
        __half2 h1 = __floats2half2_rn(v.z, v.w);
        uint2 o;
        o.x = *reinterpret_cast<uint32_t*>(&h0);
        o.y = *reinterpret_cast<uint32_t*>(&h1);
        reinterpret_cast<uint2*>(g_XH)[i] = o;
    } else {
        __shared__ float t[32][33];
        int b = blockIdx.x - XBLK;                     // 128 x 128 tile grid
        int bx = (b & 127) * 32, by = (b >> 7) * 32;   // bx: n, by: k
        int tx = threadIdx.x & 31, ty = threadIdx.x >> 5;
#pragma unroll
        for (int i = 0; i < 32; i += 8)
            t[ty + i][tx] = W[(size_t)(by + ty + i) * D_DIM + bx + tx];
        __syncthreads();
#pragma unroll
        for (int i = 0; i < 32; i += 8)
            g_WTH[(size_t)(bx + ty + i) * D_DIM + by + tx] =
                __float2half_rn(t[tx][ty + i]);
    }
}

// ---------------------------------------------------------------------------
// GEMM. grid (16, 64), 256 threads = 8 warps (2m x 4n), warp tile 64x64.
// SMEM stage: [A 128x64 | B 256x64] halves, 128B rows, granule-XOR swizzle.
// ---------------------------------------------------------------------------
__global__ __launch_bounds__(THREADS, 1)
void gemm_f16_kernel(const float* __restrict__ bias, float* __restrict__ out) {
    extern __shared__ char smem[];
    const uint32_t sbase = smem_u32(smem);
    const int tid = threadIdx.x;
    const int wid = tid >> 5;
    const int l = tid & 31;
    const int bm = blockIdx.y * BM;
    const int bn = blockIdx.x * BN;
    const int wm = (wid >> 2) * 64;   // 2 warps in m
    const int wn = (wid & 3) * 64;    // 4 warps in n

    // --- lean cp.async addressing: granule j covers row (tid>>3)+j*32 ---
    const char* a_src = (const char*)(g_XH +
        (size_t)(bm + (tid >> 3)) * D_DIM + (tid & 7) * 8);
    const char* b_src = (const char*)(g_WTH +
        (size_t)(bn + (tid >> 3)) * D_DIM + (tid & 7) * 8);
    const uint32_t sdst0 = (uint32_t)((tid >> 3) * 128) +
                           ((uint32_t)((tid & 7) ^ ((tid >> 3) & 7)) << 4);

    // chunked loader: chunk c (0..2) issues 4 of the 12 granules.
    // granules 0-3: A rows j*32; granules 4-11: B rows (j-4)*32.
    auto load_chunk = [&](int kt, int slot, int c) {
        const uint32_t sb = sbase + (uint32_t)slot * STAGE_BYTES;
        const char* ak = a_src + (size_t)kt * (BK * 2);
        const char* bk = b_src + (size_t)kt * (BK * 2);
        if (c == 0) {
#pragma unroll
            for (int j = 0; j < 4; j++)
                cp_async16(sb + sdst0 + j * 4096,
                           ak + (size_t)j * 32 * D_DIM * 2);
        } else if (c == 1) {
#pragma unroll
            for (int j = 0; j < 4; j++)
                cp_async16(sb + A_TILE_BYTES + sdst0 + j * 4096,
                           bk + (size_t)j * 32 * D_DIM * 2);
        } else {
#pragma unroll
            for (int j = 4; j < 8; j++)
                cp_async16(sb + A_TILE_BYTES + sdst0 + j * 4096,
                           bk + (size_t)j * 32 * D_DIM * 2);
        }
    };

    // --- ldmatrix addressing ---
    const int arow_l = (l & 15);
    const int akg0 = (l >> 4);
    const int brow_off = (l & 7) + ((l >> 4) << 3);
    const int bkg0 = (l >> 3) & 1;
    const uint32_t a_base = (uint32_t)((wm + arow_l) * 128);
    const uint32_t b_base = (uint32_t)((wn + brow_off) * 128) + A_TILE_BYTES;
    const uint32_t kxor = (uint32_t)(l & 7);

    auto load_frags = [&](uint32_t stg, int ks,
                          uint32_t (&A)[4][4], uint32_t (&B)[4][4]) {
#pragma unroll
        for (int mt = 0; mt < 4; mt++)
            ldsm_x4(A[mt], stg + a_base + mt * 2048 +
                           ((((uint32_t)(2 * ks) + akg0) ^ kxor) << 4));
#pragma unroll
        for (int p = 0; p < 4; p++)
            ldsm_x4(B[p], stg + b_base + p * 2048 +
                          ((((uint32_t)(2 * ks) + bkg0) ^ kxor) << 4));
    };

    float acc[4][8][4] = {};
    uint32_t Abuf[2][4][4], Bbuf[2][4][4];

    auto mma_all = [&](uint32_t (&A)[4][4], uint32_t (&B)[4][4]) {
#pragma unroll
        for (int mt = 0; mt < 4; mt++)
#pragma unroll
            for (int p = 0; p < 4; p++) {
                mma16816(acc[mt][2 * p],     A[mt], B[p][0], B[p][1]);
                mma16816(acc[mt][2 * p + 1], A[mt], B[p][2], B[p][3]);
            }
    };

    // --- prologue: fill 3 stages, arm first fragment buffer ---
#pragma unroll
    for (int s = 0; s < STAGES - 1; s++) {
        load_chunk(s, s, 0); load_chunk(s, s, 1); load_chunk(s, s, 2);
        cp_commit();
    }
    asm volatile("cp.async.wait_group %0;" :: "n"(STAGES - 2) : "memory");
    __syncthreads();
    load_frags(sbase, 0, Abuf[0], Bbuf[0]);

    for (int kt = 0; kt < KTILES; kt++) {
        const uint32_t stg = sbase + (uint32_t)(kt & 3) * STAGE_BYTES;
        const int pf = kt + STAGES - 1;
        const bool pv = pf < KTILES;
        const int pslot = pf & 3;

#pragma unroll
        for (int ks = 0; ks < 4; ks++) {
            if (ks < 3 && pv) load_chunk(pf, pslot, ks);   // spread prefetch
            if (ks < 3)
                load_frags(stg, ks + 1, Abuf[(ks + 1) & 1], Bbuf[(ks + 1) & 1]);
            mma_all(Abuf[ks & 1], Bbuf[ks & 1]);
        }
        cp_commit();

        asm volatile("cp.async.wait_group %0;" :: "n"(STAGES - 2) : "memory");
        __syncthreads();
        if (kt + 1 < KTILES)
            load_frags(sbase + (uint32_t)((kt + 1) & 3) * STAGE_BYTES, 0,
                       Abuf[0], Bbuf[0]);
    }

    // --- epilogue: y = acc + bias ---
    const int grp = l >> 2, tig = l & 3;
#pragma unroll
    for (int mt = 0; mt < 4; mt++) {
        const size_t row0 = (size_t)(bm + wm + mt * 16 + grp);
#pragma unroll
        for (int nt = 0; nt < 8; nt++) {
            const int col = bn + wn + nt * 8 + tig * 2;
            const float2 bv = *reinterpret_cast<const float2*>(bias + col);
            float2 v0, v1;
            v0.x = acc[mt][nt][0] + bv.x;
            v0.y = acc[mt][nt][1] + bv.y;
            v1.x = acc[mt][nt][2] + bv.x;
            v1.y = acc[mt][nt][3] + bv.y;
            *reinterpret_cast<float2*>(out + row0 * D_DIM + col) = v0;
            *reinterpret_cast<float2*>(out + (row0 + 8) * D_DIM + col) = v1;
        }
    }
}

// ---------------------------------------------------------------------------
// Launch
// ---------------------------------------------------------------------------
extern "C" void kernel_launch(void* const* d_in, const int* in_sizes, int n_in,
                              void* d_out, int out_size) {
    const float* x    = (const float*)d_in[0];
    const float* W    = (const float*)d_in[1];
    const float* bias = (const float*)d_in[2];
    float* out = (float*)d_out;

    cudaFuncSetAttribute(gemm_f16_kernel,
                         cudaFuncAttributeMaxDynamicSharedMemorySize, SMEM_SIZE);

    prep_kernel<<<XBLK + 128 * 128, 256>>>((const float4*)x, W);
    gemm_f16_kernel<<<dim3(D_DIM / BN, M_DIM / BM), THREADS, SMEM_SIZE>>>(
        bias, out);
}

// round 15
// speedup vs baseline: 1.5647x; 1.0114x over previous
#include <cuda_runtime.h>
#include <cuda_fp16.h>
#include <cstdint>
#include <cstddef>

// ============================================================================
// SparseLinear: y[8192,4096] = x[8192,4096] @ W[4096,4096] + bias[4096]
// Dense fp16 mma.sync GEMM (tcgen05 blocked by compute_103 PTX target;
// mma.sp runs at dense rate on this path; persistent CTAs regressed).
// R14 = R13 with the prep alignment bug fixed: t[64][65] rows are 4B-odd
//       aligned for odd n -> float2 smem read faulted; now two scalar loads.
//       GEMM unchanged: BK=128, 2-stage (32 barrier boundaries), spread
//       6-granule prefetch per ks step.
// ============================================================================

#define D_DIM 4096
#define M_DIM 8192
#define BM 128
#define BN 256
#define BK 128
#define KTILES (D_DIM / BK)            // 32
#define THREADS 256
#define A_TILE_BYTES (BM * BK * 2)     // 32768
#define B_TILE_BYTES (BN * BK * 2)     // 65536
#define STAGE_BYTES (A_TILE_BYTES + B_TILE_BYTES)   // 98304
#define SMEM_SIZE (2 * STAGE_BYTES)                 // 196608

__device__ __align__(256) __half g_XH[(size_t)M_DIM * D_DIM];
__device__ __align__(256) __half g_WTH[(size_t)D_DIM * D_DIM];

// ---------------------------------------------------------------------------
// helpers
// ---------------------------------------------------------------------------
__device__ __forceinline__ uint32_t smem_u32(const void* p) {
    uint32_t a;
    asm("{ .reg .u64 t; cvta.to.shared.u64 t, %1; cvt.u32.u64 %0, t; }"
        : "=r"(a) : "l"(p));
    return a;
}

__device__ __forceinline__ void cp_async16(uint32_t dst, const void* src) {
    asm volatile("cp.async.cg.shared.global [%0], [%1], 16;"
                 :: "r"(dst), "l"(src));
}
__device__ __forceinline__ void cp_commit() {
    asm volatile("cp.async.commit_group;" ::: "memory");
}

__device__ __forceinline__ void ldsm_x4(uint32_t* r, uint32_t addr) {
    asm volatile("ldmatrix.sync.aligned.m8n8.x4.shared.b16 {%0,%1,%2,%3}, [%4];"
                 : "=r"(r[0]), "=r"(r[1]), "=r"(r[2]), "=r"(r[3])
                 : "r"(addr));
}

__device__ __forceinline__ void mma16816(float* c, const uint32_t* a,
                                         uint32_t b0, uint32_t b1) {
    asm volatile(
        "mma.sync.aligned.m16n8k16.row.col.f32.f16.f16.f32 "
        "{%0,%1,%2,%3}, {%4,%5,%6,%7}, {%8,%9}, {%0,%1,%2,%3};"
        : "+f"(c[0]), "+f"(c[1]), "+f"(c[2]), "+f"(c[3])
        : "r"(a[0]), "r"(a[1]), "r"(a[2]), "r"(a[3]), "r"(b0), "r"(b1));
}

// ---------------------------------------------------------------------------
// Merged prep: blocks [0, XBLK2) convert x (32B/thread); rest: 64x64 W tiles.
// ---------------------------------------------------------------------------
#define XBLK2 ((int)((size_t)M_DIM * D_DIM / 8 / 256))   // 16384

__global__ void prep_kernel(const float4* __restrict__ x,
                            const float* __restrict__ W) {
    if (blockIdx.x < XBLK2) {
        size_t i = (size_t)blockIdx.x * 256 + threadIdx.x;
        float4 v0 = x[2 * i];
        float4 v1 = x[2 * i + 1];
        __half2 h0 = __floats2half2_rn(v0.x, v0.y);
        __half2 h1 = __floats2half2_rn(v0.z, v0.w);
        __half2 h2 = __floats2half2_rn(v1.x, v1.y);
        __half2 h3 = __floats2half2_rn(v1.z, v1.w);
        uint4 o;
        o.x = *reinterpret_cast<uint32_t*>(&h0);
        o.y = *reinterpret_cast<uint32_t*>(&h1);
        o.z = *reinterpret_cast<uint32_t*>(&h2);
        o.w = *reinterpret_cast<uint32_t*>(&h3);
        reinterpret_cast<uint4*>(g_XH)[i] = o;
    } else {
        __shared__ float t[64][65];    // t[n_local][k_local]
        int b = blockIdx.x - XBLK2;                    // 64 x 64 tile grid
        int bx = (b & 63) * 64, by = (b >> 6) * 64;    // bx: n, by: k
        const int nx = threadIdx.x & 63, ky = threadIdx.x >> 6;
#pragma unroll
        for (int i = 0; i < 16; i++)
            t[nx][ky + i * 4] = W[(size_t)(by + ky + i * 4) * D_DIM + bx + nx];
        __syncthreads();
#pragma unroll
        for (int i = 0; i < 8; i++) {
            int idx = threadIdx.x + i * 256;
            int nl = idx >> 5, c = idx & 31;
            // scalar loads: rows of t are only 4B-aligned for odd nl
            float va = t[nl][2 * c];
            float vb = t[nl][2 * c + 1];
            __half2 h = __floats2half2_rn(va, vb);
            *reinterpret_cast<uint32_t*>(
                g_WTH + (size_t)(bx + nl) * D_DIM + by + 2 * c) =
                *reinterpret_cast<uint32_t*>(&h);
        }
    }
}

// ---------------------------------------------------------------------------
// GEMM. grid (16, 64), 256 threads = 8 warps (2m x 4n), warp tile 64x64.
// SMEM stage: [A 128x128 | B 256x128] halves, 256B rows, granule-XOR swizzle
// (XOR on low 3 granule bits only -> same conflict-free pattern as BK=64).
// 2-stage: tile kt+1 streams into the other slot during kt's 8 ks steps.
// ---------------------------------------------------------------------------
__global__ __launch_bounds__(THREADS, 1)
void gemm_f16_kernel(const float* __restrict__ bias, float* __restrict__ out) {
    extern __shared__ char smem[];
    const uint32_t sbase = smem_u32(smem);
    const int tid = threadIdx.x;
    const int wid = tid >> 5;
    const int l = tid & 31;
    const int bm = blockIdx.y * BM;
    const int bn = blockIdx.x * BN;
    const int wm = (wid >> 2) * 64;   // 2 warps in m
    const int wn = (wid & 3) * 64;    // 4 warps in n

    // --- cp.async addressing: thread owns granule col g=tid&15, rows r0+16j
    const int r0 = tid >> 4;           // 0..15
    const int g0 = tid & 15;           // 16B granule within 256B row
    const char* a_src = (const char*)(g_XH + (size_t)(bm + r0) * D_DIM + g0 * 8);
    const char* b_src = (const char*)(g_WTH + (size_t)(bn + r0) * D_DIM + g0 * 8);
    const uint32_t sdst0 = (uint32_t)(r0 * 256) +
                           ((uint32_t)(g0 ^ (r0 & 7)) << 4);
    // row step per j: +16 rows = +4096B smem, +16*D halves gmem
    const size_t gstep = (size_t)16 * D_DIM * 2;

    // chunk c in 0..3 issues 6 of 24 granules (A j0..7, B j0..15)
    auto load_chunk = [&](int kt, uint32_t sb, int c) {
        const char* ak = a_src + (size_t)kt * 256;
        const char* bk = b_src + (size_t)kt * 256;
        if (c == 0) {
#pragma unroll
            for (int j = 0; j < 6; j++)
                cp_async16(sb + sdst0 + j * 4096, ak + (size_t)j * gstep);
        } else if (c == 1) {
#pragma unroll
            for (int j = 6; j < 8; j++)
                cp_async16(sb + sdst0 + j * 4096, ak + (size_t)j * gstep);
#pragma unroll
            for (int j = 0; j < 4; j++)
                cp_async16(sb + A_TILE_BYTES + sdst0 + j * 4096,
                           bk + (size_t)j * gstep);
        } else if (c == 2) {
#pragma unroll
            for (int j = 4; j < 10; j++)
                cp_async16(sb + A_TILE_BYTES + sdst0 + j * 4096,
                           bk + (size_t)j * gstep);
        } else {
#pragma unroll
            for (int j = 10; j < 16; j++)
                cp_async16(sb + A_TILE_BYTES + sdst0 + j * 4096,
                           bk + (size_t)j * gstep);
        }
    };

    // --- ldmatrix addressing (256B rows) ---
    const int arow_l = (l & 15);
    const int akg0 = (l >> 4);
    const int brow_off = (l & 7) + ((l >> 4) << 3);
    const int bkg0 = (l >> 3) & 1;
    const uint32_t a_base = (uint32_t)((wm + arow_l) * 256);
    const uint32_t b_base = (uint32_t)((wn + brow_off) * 256) + A_TILE_BYTES;
    const uint32_t kxor = (uint32_t)(l & 7);

    auto load_frags = [&](uint32_t stg, int ks,
                          uint32_t (&A)[4][4], uint32_t (&B)[4][4]) {
#pragma unroll
        for (int mt = 0; mt < 4; mt++)
            ldsm_x4(A[mt], stg + a_base + mt * 4096 +
                           ((((uint32_t)(2 * ks) + akg0) ^ kxor) << 4));
#pragma unroll
        for (int p = 0; p < 4; p++)
            ldsm_x4(B[p], stg + b_base + p * 4096 +
                          ((((uint32_t)(2 * ks) + bkg0) ^ kxor) << 4));
    };

    float acc[4][8][4] = {};
    uint32_t Abuf[2][4][4], Bbuf[2][4][4];

    auto mma_all = [&](uint32_t (&A)[4][4], uint32_t (&B)[4][4]) {
#pragma unroll
        for (int mt = 0; mt < 4; mt++)
#pragma unroll
            for (int p = 0; p < 4; p++) {
                mma16816(acc[mt][2 * p],     A[mt], B[p][0], B[p][1]);
                mma16816(acc[mt][2 * p + 1], A[mt], B[p][2], B[p][3]);
            }
    };

    // --- prologue: load tile 0 into slot 0 ---
#pragma unroll
    for (int c = 0; c < 4; c++) load_chunk(0, sbase, c);
    cp_commit();
    asm volatile("cp.async.wait_group 0;" ::: "memory");
    __syncthreads();
    load_frags(sbase, 0, Abuf[0], Bbuf[0]);

    for (int kt = 0; kt < KTILES; kt++) {
        const uint32_t stg = sbase + (uint32_t)(kt & 1) * STAGE_BYTES;
        const uint32_t oth = sbase + (uint32_t)((kt + 1) & 1) * STAGE_BYTES;
        const bool pv = (kt + 1) < KTILES;

#pragma unroll
        for (int ks = 0; ks < 8; ks++) {
            if (ks < 4 && pv) load_chunk(kt + 1, oth, ks);
            if (ks < 7)
                load_frags(stg, ks + 1, Abuf[(ks + 1) & 1], Bbuf[(ks + 1) & 1]);
            mma_all(Abuf[ks & 1], Bbuf[ks & 1]);
        }
        cp_commit();
        asm volatile("cp.async.wait_group 0;" ::: "memory");
        __syncthreads();
        if (pv) load_frags(oth, 0, Abuf[0], Bbuf[0]);
    }

    // --- epilogue: y = acc + bias ---
    const int grp = l >> 2, tig = l & 3;
#pragma unroll
    for (int mt = 0; mt < 4; mt++) {
        const size_t row0 = (size_t)(bm + wm + mt * 16 + grp);
#pragma unroll
        for (int nt = 0; nt < 8; nt++) {
            const int col = bn + wn + nt * 8 + tig * 2;
            const float2 bv = *reinterpret_cast<const float2*>(bias + col);
            float2 v0, v1;
            v0.x = acc[mt][nt][0] + bv.x;
            v0.y = acc[mt][nt][1] + bv.y;
            v1.x = acc[mt][nt][2] + bv.x;
            v1.y = acc[mt][nt][3] + bv.y;
            *reinterpret_cast<float2*>(out + row0 * D_DIM + col) = v0;
            *reinterpret_cast<float2*>(out + (row0 + 8) * D_DIM + col) = v1;
        }
    }
}

// ---------------------------------------------------------------------------
// Launch
// ---------------------------------------------------------------------------
extern "C" void kernel_launch(void* const* d_in, const int* in_sizes, int n_in,
                              void* d_out, int out_size) {
    const float* x    = (const float*)d_in[0];
    const float* W    = (const float*)d_in[1];
    const float* bias = (const float*)d_in[2];
    float* out = (float*)d_out;

    cudaFuncSetAttribute(gemm_f16_kernel,
                         cudaFuncAttributeMaxDynamicSharedMemorySize, SMEM_SIZE);

    prep_kernel<<<XBLK2 + 64 * 64, 256>>>((const float4*)x, W);
    gemm_f16_kernel<<<dim3(D_DIM / BN, M_DIM / BM), THREADS, SMEM_SIZE>>>(
        bias, out);
}